// round 14
// baseline (speedup 1.0000x reference)
#include <cuda_runtime.h>
#include <cuda_bf16.h>
#include <cuda_fp16.h>
#include <cstdint>

#define N_NODES 100000
#define N_EDGES 1600000
#define D 128
#define NEG_SLOPE 0.2f
#define BUCKET 96           // max degree supported; Poisson(16) => P(deg>96) ~ 1e-30
#define CAP 3               // BUCKET/32

// ---------------- scratch (device globals: no allocation allowed) ----------------
__device__ __half2  g_h16[(size_t)N_NODES * (D / 2)];   // 25.6 MB fp16 h (256B/row)
__device__ float    g_el[N_NODES];
__device__ float    g_er[N_NODES];
__device__ float    g_wl[D];
__device__ float    g_wr[D];
__device__ unsigned g_cur[N_NODES];                     // per-node fill cursor / degree
__device__ int      g_csrc[(size_t)N_NODES * BUCKET];   // 38.4 MB padded CSR (src)
__device__ float    g_eb[(size_t)N_NODES * BUCKET];     // 38.4 MB padded CSR (logit e)

// ---------------- bf16 split helpers ----------------
__device__ __forceinline__ unsigned pack_bf16x2(float e0, float e1) {
    unsigned r;
    asm("cvt.rn.bf16x2.f32 %0, %1, %2;" : "=r"(r) : "f"(e1), "f"(e0));
    return r;  // low half = e0
}
__device__ __forceinline__ float bf16lo_f(unsigned u) { return __uint_as_float(u << 16); }
__device__ __forceinline__ float bf16hi_f(unsigned u) { return __uint_as_float(u & 0xffff0000u); }

__device__ __forceinline__ uint2 split_pack(float2 v) {
    unsigned hi = pack_bf16x2(v.x, v.y);
    unsigned lo = pack_bf16x2(v.x - bf16lo_f(hi), v.y - bf16hi_f(hi));
    return make_uint2(hi, lo);
}

__device__ __forceinline__ void mma_bf16(float c[4], const unsigned a[4],
                                         unsigned b0, unsigned b1) {
    asm volatile(
        "mma.sync.aligned.m16n8k16.row.col.f32.bf16.bf16.f32 "
        "{%0,%1,%2,%3}, {%4,%5,%6,%7}, {%8,%9}, {%0,%1,%2,%3};"
        : "+f"(c[0]), "+f"(c[1]), "+f"(c[2]), "+f"(c[3])
        : "r"(a[0]), "r"(a[1]), "r"(a[2]), "r"(a[3]), "r"(b0), "r"(b1));
}

// ---------------- K1: h = x @ W^T via bf16x3 mma (fp16 h out) ----------------
#define CSTRIDE 36
#define CHUNK_KP 32
__global__ __launch_bounds__(256, 2) void k_gemm_tc(const float* __restrict__ x,
                                                    const float* __restrict__ W,
                                                    int n) {
    extern __shared__ uint2 sbuf[];
    uint2* xs = sbuf;                      // [128][CSTRIDE]
    uint2* ws = sbuf + 128 * CSTRIDE;      // [128][CSTRIDE]
    const int tid = threadIdx.x;
    const int row0 = blockIdx.x * 128;

    const int wid = tid >> 5, lane = tid & 31;
    const int g = lane >> 2, t = lane & 3;
    const int m0 = wid * 16;
    const int rA = row0 + m0 + g;
    const int rB = rA + 8;
    const bool okA = rA < n, okB = rB < n;

    float c[16][4];
#pragma unroll
    for (int nt = 0; nt < 16; ++nt)
#pragma unroll
        for (int j = 0; j < 4; ++j) c[nt][j] = 0.0f;

#pragma unroll
    for (int ch = 0; ch < 2; ++ch) {
        const int col0 = ch * (CHUNK_KP * 2);

#pragma unroll
        for (int i = 0; i < 16; ++i) {
            int idx = tid + i * 256;
            int r = idx >> 5, kp = idx & 31;
            int row = row0 + r;
            float2 v = (row < n) ? *(const float2*)(x + (size_t)row * D + col0 + kp * 2)
                                 : make_float2(0.f, 0.f);
            xs[r * CSTRIDE + kp] = split_pack(v);
        }
#pragma unroll
        for (int i = 0; i < 16; ++i) {
            int idx = tid + i * 256;
            int r = idx >> 5, kp = idx & 31;
            float2 v = *(const float2*)(W + (size_t)r * D + col0 + kp * 2);
            ws[r * CSTRIDE + kp] = split_pack(v);
        }
        __syncthreads();

        const uint2* xrA = xs + (m0 + g) * CSTRIDE;
        const uint2* xrB = xs + (m0 + g + 8) * CSTRIDE;

#pragma unroll
        for (int kc = 0; kc < 4; ++kc) {
            const int kp0 = kc * 8 + t;
            uint2 pA0 = xrA[kp0], pB0 = xrB[kp0];
            uint2 pA4 = xrA[kp0 + 4], pB4 = xrB[kp0 + 4];
            unsigned ahi[4] = {pA0.x, pB0.x, pA4.x, pB4.x};
            unsigned alo[4] = {pA0.y, pB0.y, pA4.y, pB4.y};

            const uint2* wbase = ws + g * CSTRIDE + kp0;
#pragma unroll
            for (int ntg = 0; ntg < 4; ++ntg) {
                uint2 b0[4], b1[4];
#pragma unroll
                for (int j = 0; j < 4; ++j) {
                    const uint2* wr = wbase + (ntg * 4 + j) * (8 * CSTRIDE);
                    b0[j] = wr[0];
                    b1[j] = wr[4];
                }
                const int nb = ntg * 4;
#pragma unroll
                for (int j = 0; j < 4; ++j)
                    mma_bf16(c[nb + j], ahi, b0[j].x, b1[j].x);
#pragma unroll
                for (int j = 0; j < 4; ++j)
                    mma_bf16(c[nb + j], ahi, b0[j].y, b1[j].y);
#pragma unroll
                for (int j = 0; j < 4; ++j)
                    mma_bf16(c[nb + j], alo, b0[j].x, b1[j].x);
            }
        }
        __syncthreads();
    }

#pragma unroll
    for (int nt = 0; nt < 16; ++nt) {
        int col = nt * 8 + 2 * t;
        if (okA) g_h16[(size_t)rA * (D / 2) + (col >> 1)] =
                     __floats2half2_rn(c[nt][0], c[nt][1]);
        if (okB) g_h16[(size_t)rB * (D / 2) + (col >> 1)] =
                     __floats2half2_rn(c[nt][2], c[nt][3]);
    }
}

// ---------------- K2a: wl = W^T a_left, wr = W^T a_right ----------------
__global__ void k_wvec(const float* __restrict__ W, const float* __restrict__ al,
                       const float* __restrict__ ar) {
    int k = threadIdx.x;   // 0..127
    float sl = 0.f, sr = 0.f;
#pragma unroll 8
    for (int j = 0; j < D; ++j) {
        float w = W[(size_t)j * D + k];
        sl += al[j] * w;
        sr += ar[j] * w;
    }
    g_wl[k] = sl;
    g_wr[k] = sr;
}

// ---------------- K2b: el = x.wl, er = x.wr (fp32 GEMV, warp/node) ----------------
__global__ __launch_bounds__(256) void k_gemv(const float* __restrict__ x, int n) {
    int node = (blockIdx.x * blockDim.x + threadIdx.x) >> 5;
    int lane = threadIdx.x & 31;
    if (node >= n) return;
    float4 xv = *(const float4*)(x + (size_t)node * D + lane * 4);
    float4 a  = *(const float4*)(g_wl + lane * 4);
    float4 b  = *(const float4*)(g_wr + lane * 4);
    float pl = xv.x * a.x + xv.y * a.y + xv.z * a.z + xv.w * a.w;
    float pr = xv.x * b.x + xv.y * b.y + xv.z * b.z + xv.w * b.w;
#pragma unroll
    for (int o = 16; o > 0; o >>= 1) {
        pl += __shfl_xor_sync(0xffffffffu, pl, o);
        pr += __shfl_xor_sync(0xffffffffu, pr, o);
    }
    if (lane == 0) { g_el[node] = pl; g_er[node] = pr; }
}

// ---------------- K3: binning + logit computation ----------------
// Stores src AND the finished leaky-ReLU logit e into the bucket, so the node
// kernel's softmax phase reads only coalesced bucket data (no scattered el gather).
__global__ void k_bin(const int* __restrict__ src, const int* __restrict__ dst, int E) {
    int i = blockIdx.x * blockDim.x + threadIdx.x;
    if (i < E) {
        int s = src[i], d = dst[i];
        unsigned slot = atomicAdd(&g_cur[d], 1u);
        if (slot < BUCKET) {
            float e = g_el[s] + g_er[d];
            e = (e >= 0.0f) ? e : NEG_SLOPE * e;
            size_t idx = (size_t)d * BUCKET + slot;
            g_csrc[idx] = s;
            g_eb[idx]   = e;
        }
    }
}

// ---------------- K4: per-node softmax + weighted gather (1 warp / node) ----------------
__global__ __launch_bounds__(256) void k_node(float* __restrict__ out, int n) {
    int node = (blockIdx.x * blockDim.x + threadIdx.x) >> 5;
    int lane = threadIdx.x & 31;
    if (node >= n) return;

    int deg = (int)g_cur[node];
    if (deg > BUCKET) deg = BUCKET;
    int nit = (deg + 31) >> 5;
    const int*   bp = g_csrc + (size_t)node * BUCKET;
    const float* ep = g_eb   + (size_t)node * BUCKET;

    float exv[CAP];
    int   sv[CAP];
    float mx = __int_as_float(0xff800000);  // -inf

    // coalesced bucket reads: e and src
#pragma unroll
    for (int it = 0; it < CAP; ++it) {
        if (it >= nit) break;
        int k = it * 32 + lane;
        bool ok = k < deg;
        float e = ok ? ep[k] : __int_as_float(0xff800000);
        sv[it]  = ok ? bp[k] : 0;
        exv[it] = e;
        mx = fmaxf(mx, e);
    }
#pragma unroll
    for (int o = 16; o > 0; o >>= 1)
        mx = fmaxf(mx, __shfl_xor_sync(0xffffffffu, mx, o));

    float den = 0.0f;
#pragma unroll
    for (int it = 0; it < CAP; ++it) {
        if (it >= nit) break;
        float ex = __expf(exv[it] - mx);   // -inf pad lanes -> 0
        exv[it] = ex;
        den += ex;
    }
#pragma unroll
    for (int o = 16; o > 0; o >>= 1)
        den += __shfl_xor_sync(0xffffffffu, den, o);
    float inv = 1.0f / fmaxf(den, 1e-38f);

    // ---- gather: 2 edges per step, 8-edge batches, LDG.128 ----
    const int half = lane >> 4;
    const int fl   = lane & 15;         // feature slice: cols fl*8 .. fl*8+7
    const char* hbase = (const char*)g_h16;
    float acc[8];
#pragma unroll
    for (int j = 0; j < 8; ++j) acc[j] = 0.0f;

#pragma unroll
    for (int it = 0; it < CAP; ++it) {
        if (it >= nit) break;
        int cnt = deg - it * 32;
        if (cnt > 32) cnt = 32;
        float exn = exv[it];            // pad lanes already 0 weight
        int   sn  = sv[it];
        for (int b = 0; b < cnt; b += 8) {
            float a[4]; int s[4];
#pragma unroll
            for (int j = 0; j < 4; ++j) {
                int e = b + 2 * j + half;               // <= 31
                float aa = __shfl_sync(0xffffffffu, exn, e) * inv;
                int   ss = __shfl_sync(0xffffffffu, sn, e);
                bool ok = e < cnt;
                a[j] = ok ? aa : 0.0f;
                s[j] = ok ? ss : 0;
            }
            uint4 u[4];
#pragma unroll
            for (int j = 0; j < 4; ++j)
                u[j] = *(const uint4*)(hbase + (size_t)s[j] * 256 + fl * 16);
#pragma unroll
            for (int j = 0; j < 4; ++j) {
                float2 f0 = __half22float2(*(__half2*)&u[j].x);
                float2 f1 = __half22float2(*(__half2*)&u[j].y);
                float2 f2 = __half22float2(*(__half2*)&u[j].z);
                float2 f3 = __half22float2(*(__half2*)&u[j].w);
                acc[0] += a[j] * f0.x; acc[1] += a[j] * f0.y;
                acc[2] += a[j] * f1.x; acc[3] += a[j] * f1.y;
                acc[4] += a[j] * f2.x; acc[5] += a[j] * f2.y;
                acc[6] += a[j] * f3.x; acc[7] += a[j] * f3.y;
            }
        }
    }

#pragma unroll
    for (int j = 0; j < 8; ++j)
        acc[j] += __shfl_xor_sync(0xffffffffu, acc[j], 16);

    if (half == 0) {
        float* op = out + (size_t)node * D + fl * 8;
        *(float4*)op       = make_float4(acc[0], acc[1], acc[2], acc[3]);
        *(float4*)(op + 4) = make_float4(acc[4], acc[5], acc[6], acc[7]);
    }
}

// ---------------- launch (two-stream fork/join, capture-safe) ----------------
#define GEMM_SMEM (2 * 128 * CSTRIDE * (int)sizeof(uint2))   // 73.7 KB

struct AsyncCtx {
    cudaStream_t s1;
    cudaEvent_t  e_fork, e_join;
    void*        cur_ptr;
    AsyncCtx() {
        cudaStreamCreateWithFlags(&s1, cudaStreamNonBlocking);
        cudaEventCreateWithFlags(&e_fork, cudaEventDisableTiming);
        cudaEventCreateWithFlags(&e_join, cudaEventDisableTiming);
        cudaGetSymbolAddress(&cur_ptr, g_cur);
        cudaFuncSetAttribute(k_gemm_tc, cudaFuncAttributeMaxDynamicSharedMemorySize,
                             GEMM_SMEM);
    }
};

extern "C" void kernel_launch(void* const* d_in, const int* in_sizes, int n_in,
                              void* d_out, int out_size) {
    static AsyncCtx ctx;   // built on first (non-captured) correctness call

    const float* x   = (const float*)d_in[0];
    const int*   src = (const int*)d_in[1];
    const int*   dst = (const int*)d_in[2];
    const float* W   = (const float*)d_in[3];
    const float* al  = (const float*)d_in[4];
    const float* ar  = (const float*)d_in[5];
    float* out = (float*)d_out;

    const int n = in_sizes[0] / D;     // 100000
    const int E = in_sizes[1];         // 1600000

    cudaEventRecord(ctx.e_fork, 0);
    cudaStreamWaitEvent(ctx.s1, ctx.e_fork, 0);

    // s1: bf16x3 tensor-core GEMM -> h16
    k_gemm_tc<<<(n + 127) / 128, 256, GEMM_SMEM, ctx.s1>>>(x, W, n);
    cudaEventRecord(ctx.e_join, ctx.s1);

    // stream 0: logits + binning (independent of GEMM, hidden under it)
    cudaMemsetAsync(ctx.cur_ptr, 0, (size_t)n * sizeof(unsigned), 0);
    k_wvec<<<1, D>>>(W, al, ar);
    k_gemv<<<(n * 32 + 255) / 256, 256>>>(x, n);
    k_bin<<<(E + 255) / 256, 256>>>(src, dst, E);

    // join: node kernel needs h16 (s1) + buckets (stream 0)
    cudaStreamWaitEvent(0, ctx.e_join, 0);
    k_node<<<(n * 32 + 255) / 256, 256>>>(out, n);
}

// round 16
// speedup vs baseline: 1.2801x; 1.2801x over previous
#include <cuda_runtime.h>
#include <cuda_bf16.h>
#include <cuda_fp16.h>
#include <cstdint>

#define N_NODES 100000
#define N_EDGES 1600000
#define D 128
#define NEG_SLOPE 0.2f
#define BUCKET 96           // max degree supported; Poisson(16) => P(deg>96) ~ 1e-30
#define CAP 3               // BUCKET/32

// ---------------- scratch (device globals: no allocation allowed) ----------------
__device__ __half2  g_h16[(size_t)N_NODES * (D / 2)];  // 25.6 MB fp16 h (256B/row)
__device__ float    g_el[N_NODES];
__device__ float    g_er[N_NODES];
__device__ unsigned g_cur[N_NODES];                    // per-node fill cursor / degree
__device__ int      g_csrc[(size_t)N_NODES * BUCKET];  // 38.4 MB padded CSR

// ---------------- bf16 split helpers ----------------
__device__ __forceinline__ unsigned pack_bf16x2(float e0, float e1) {
    unsigned r;
    asm("cvt.rn.bf16x2.f32 %0, %1, %2;" : "=r"(r) : "f"(e1), "f"(e0));
    return r;  // low half = e0
}
__device__ __forceinline__ float bf16lo_f(unsigned u) { return __uint_as_float(u << 16); }
__device__ __forceinline__ float bf16hi_f(unsigned u) { return __uint_as_float(u & 0xffff0000u); }

__device__ __forceinline__ uint2 split_pack(float2 v) {
    unsigned hi = pack_bf16x2(v.x, v.y);
    unsigned lo = pack_bf16x2(v.x - bf16lo_f(hi), v.y - bf16hi_f(hi));
    return make_uint2(hi, lo);
}

__device__ __forceinline__ void mma_bf16(float c[4], const unsigned a[4],
                                         unsigned b0, unsigned b1) {
    asm volatile(
        "mma.sync.aligned.m16n8k16.row.col.f32.bf16.bf16.f32 "
        "{%0,%1,%2,%3}, {%4,%5,%6,%7}, {%8,%9}, {%0,%1,%2,%3};"
        : "+f"(c[0]), "+f"(c[1]), "+f"(c[2]), "+f"(c[3])
        : "r"(a[0]), "r"(a[1]), "r"(a[2]), "r"(a[3]), "r"(b0), "r"(b1));
}

// ---------------- K1: h = x @ W^T via bf16x3 mma + fused el/er dots ----------------
// block = 256 threads (8 warps), 2 blocks/SM. Tile M=128 (16 rows/warp), N=128.
// K processed in 2 chunks of 64; per chunk both A and W staged as packed
// (hi,lo) bf16x2 uint2, row stride 36 (conflict-free fragment loads + stores).
#define CSTRIDE 36
#define CHUNK_KP 32   // k-pairs per chunk (64 K values)
__global__ __launch_bounds__(256, 2) void k_gemm_tc(const float* __restrict__ x,
                                                    const float* __restrict__ W,
                                                    const float* __restrict__ al,
                                                    const float* __restrict__ ar,
                                                    int n) {
    extern __shared__ uint2 sbuf[];
    uint2* xs = sbuf;                      // [128][CSTRIDE]
    uint2* ws = sbuf + 128 * CSTRIDE;      // [128][CSTRIDE]
    const int tid = threadIdx.x;
    const int row0 = blockIdx.x * 128;

    const int wid = tid >> 5, lane = tid & 31;
    const int g = lane >> 2, t = lane & 3;
    const int m0 = wid * 16;
    const int rA = row0 + m0 + g;
    const int rB = rA + 8;
    const bool okA = rA < n, okB = rB < n;

    float c[16][4];
#pragma unroll
    for (int nt = 0; nt < 16; ++nt)
#pragma unroll
        for (int j = 0; j < 4; ++j) c[nt][j] = 0.0f;

#pragma unroll
    for (int ch = 0; ch < 2; ++ch) {
        const int col0 = ch * (CHUNK_KP * 2);   // float column base of this chunk

        // stage A chunk: 128 rows x 32 kp = 4096 uint2 (16 iters)
#pragma unroll
        for (int i = 0; i < 16; ++i) {
            int idx = tid + i * 256;
            int r = idx >> 5, kp = idx & 31;
            int row = row0 + r;
            float2 v = (row < n) ? *(const float2*)(x + (size_t)row * D + col0 + kp * 2)
                                 : make_float2(0.f, 0.f);
            xs[r * CSTRIDE + kp] = split_pack(v);
        }
        // stage W chunk
#pragma unroll
        for (int i = 0; i < 16; ++i) {
            int idx = tid + i * 256;
            int r = idx >> 5, kp = idx & 31;
            float2 v = *(const float2*)(W + (size_t)r * D + col0 + kp * 2);
            ws[r * CSTRIDE + kp] = split_pack(v);
        }
        __syncthreads();

        const uint2* xrA = xs + (m0 + g) * CSTRIDE;
        const uint2* xrB = xs + (m0 + g + 8) * CSTRIDE;

#pragma unroll
        for (int kc = 0; kc < 4; ++kc) {
            const int kp0 = kc * 8 + t;
            uint2 pA0 = xrA[kp0], pB0 = xrB[kp0];
            uint2 pA4 = xrA[kp0 + 4], pB4 = xrB[kp0 + 4];
            unsigned ahi[4] = {pA0.x, pB0.x, pA4.x, pB4.x};
            unsigned alo[4] = {pA0.y, pB0.y, pA4.y, pB4.y};

            const uint2* wrow = ws + g * CSTRIDE + kp0;
            // 2-nt interleave: consecutive same-accumulator MMAs are 2 apart
#pragma unroll
            for (int nt = 0; nt < 16; nt += 2) {
                uint2 b0a = wrow[0];
                uint2 b1a = wrow[4];
                uint2 b0b = wrow[8 * CSTRIDE];
                uint2 b1b = wrow[8 * CSTRIDE + 4];
                wrow += 16 * CSTRIDE;
                mma_bf16(c[nt],     ahi, b0a.x, b1a.x);   // hh nt
                mma_bf16(c[nt + 1], ahi, b0b.x, b1b.x);   // hh nt+1
                mma_bf16(c[nt],     ahi, b0a.y, b1a.y);   // hl nt
                mma_bf16(c[nt + 1], ahi, b0b.y, b1b.y);   // hl nt+1
                mma_bf16(c[nt],     alo, b0a.x, b1a.x);   // lh nt
                mma_bf16(c[nt + 1], alo, b0b.x, b1b.x);   // lh nt+1
            }
        }
        __syncthreads();
    }

    // epilogue: store h as fp16 + fused dots (C frag: rows rA/rB, cols nt*8+2t,+1)
    float plA = 0.f, prA = 0.f, plB = 0.f, prB = 0.f;
#pragma unroll
    for (int nt = 0; nt < 16; ++nt) {
        int col = nt * 8 + 2 * t;
        float2 av = *(const float2*)(al + col);
        float2 rv = *(const float2*)(ar + col);
        plA += c[nt][0] * av.x + c[nt][1] * av.y;
        prA += c[nt][0] * rv.x + c[nt][1] * rv.y;
        plB += c[nt][2] * av.x + c[nt][3] * av.y;
        prB += c[nt][2] * rv.x + c[nt][3] * rv.y;
        if (okA) g_h16[(size_t)rA * (D / 2) + (col >> 1)] =
                     __floats2half2_rn(c[nt][0], c[nt][1]);
        if (okB) g_h16[(size_t)rB * (D / 2) + (col >> 1)] =
                     __floats2half2_rn(c[nt][2], c[nt][3]);
    }
#pragma unroll
    for (int o = 1; o < 4; o <<= 1) {
        plA += __shfl_xor_sync(0xffffffffu, plA, o);
        prA += __shfl_xor_sync(0xffffffffu, prA, o);
        plB += __shfl_xor_sync(0xffffffffu, plB, o);
        prB += __shfl_xor_sync(0xffffffffu, prB, o);
    }
    if (t == 0) {
        if (okA) { g_el[rA] = plA; g_er[rA] = prA; }
        if (okB) { g_el[rB] = plB; g_er[rB] = prB; }
    }
}

// ---------------- K2: direct binning into padded buckets ----------------
__global__ void k_bin(const int* __restrict__ src, const int* __restrict__ dst, int E) {
    int i = blockIdx.x * blockDim.x + threadIdx.x;
    if (i < E) {
        int d = dst[i];
        unsigned slot = atomicAdd(&g_cur[d], 1u);
        if (slot < BUCKET) g_csrc[(size_t)d * BUCKET + slot] = src[i];
    }
}

// ---------------- K3: per-node softmax + weighted gather (1 warp / node) ----------------
// Gather phase: warp split into two 16-lane halves; each half owns alternate
// edges; each lane owns an 8-feature slice (uint4 = 8 fp16, LDG.128).
__global__ __launch_bounds__(256) void k_node(float* __restrict__ out, int n) {
    int node = (blockIdx.x * blockDim.x + threadIdx.x) >> 5;
    int lane = threadIdx.x & 31;
    if (node >= n) return;

    int deg = (int)g_cur[node];
    if (deg > BUCKET) deg = BUCKET;
    const int* bp = g_csrc + (size_t)node * BUCKET;
    float er_d = g_er[node];
    int nit = (deg + 31) >> 5;

    float exv[CAP];
    int   sv[CAP];
    float mx = __int_as_float(0xff800000);  // -inf

#pragma unroll
    for (int it = 0; it < CAP; ++it) {
        if (it >= nit) break;
        int k = it * 32 + lane;
        float e = __int_as_float(0xff800000);
        int s = 0;
        if (k < deg) {
            s = bp[k];
            e = g_el[s] + er_d;
            e = (e >= 0.0f) ? e : NEG_SLOPE * e;
        }
        sv[it] = s;
        exv[it] = e;
        mx = fmaxf(mx, e);
    }
#pragma unroll
    for (int o = 16; o > 0; o >>= 1)
        mx = fmaxf(mx, __shfl_xor_sync(0xffffffffu, mx, o));

    float den = 0.0f;
#pragma unroll
    for (int it = 0; it < CAP; ++it) {
        if (it >= nit) break;
        float ex = __expf(exv[it] - mx);
        exv[it] = ex;
        den += ex;
    }
#pragma unroll
    for (int o = 16; o > 0; o >>= 1)
        den += __shfl_xor_sync(0xffffffffu, den, o);
    float inv = 1.0f / fmaxf(den, 1e-38f);

    // ---- gather: 2 edges per step, 8-edge batches ----
    const int half = lane >> 4;         // 0/1: which edge of each pair
    const int fl   = lane & 15;         // feature slice: cols fl*8 .. fl*8+7
    const char* hbase = (const char*)g_h16;
    float acc[8];
#pragma unroll
    for (int j = 0; j < 8; ++j) acc[j] = 0.0f;

#pragma unroll
    for (int it = 0; it < CAP; ++it) {
        if (it >= nit) break;
        int cnt = deg - it * 32;
        if (cnt > 32) cnt = 32;
        float exn = exv[it];
        int   sn  = sv[it];
        for (int b = 0; b < cnt; b += 8) {
            float a[4]; int s[4];
#pragma unroll
            for (int j = 0; j < 4; ++j) {
                int e = b + 2 * j + half;           // <= 31
                float aa = __shfl_sync(0xffffffffu, exn, e) * inv;
                int   ss = __shfl_sync(0xffffffffu, sn, e);
                bool ok = e < cnt;
                a[j] = ok ? aa : 0.0f;
                s[j] = ok ? ss : 0;                 // row 0 valid; a=0 kills it
            }
            uint4 u[4];
#pragma unroll
            for (int j = 0; j < 4; ++j)
                u[j] = *(const uint4*)(hbase + (size_t)s[j] * 256 + fl * 16);
#pragma unroll
            for (int j = 0; j < 4; ++j) {
                float2 f0 = __half22float2(*(__half2*)&u[j].x);
                float2 f1 = __half22float2(*(__half2*)&u[j].y);
                float2 f2 = __half22float2(*(__half2*)&u[j].z);
                float2 f3 = __half22float2(*(__half2*)&u[j].w);
                acc[0] += a[j] * f0.x; acc[1] += a[j] * f0.y;
                acc[2] += a[j] * f1.x; acc[3] += a[j] * f1.y;
                acc[4] += a[j] * f2.x; acc[5] += a[j] * f2.y;
                acc[6] += a[j] * f3.x; acc[7] += a[j] * f3.y;
            }
        }
    }

    // merge the two halves (lane f and lane f+16 hold partial sums of same slice)
#pragma unroll
    for (int j = 0; j < 8; ++j)
        acc[j] += __shfl_xor_sync(0xffffffffu, acc[j], 16);

    if (half == 0) {
        float* op = out + (size_t)node * D + fl * 8;
        *(float4*)op       = make_float4(acc[0], acc[1], acc[2], acc[3]);
        *(float4*)(op + 4) = make_float4(acc[4], acc[5], acc[6], acc[7]);
    }
}

// ---------------- launch (two-stream fork/join, capture-safe) ----------------
#define GEMM_SMEM (2 * 128 * CSTRIDE * (int)sizeof(uint2))   // 73.7 KB

struct AsyncCtx {
    cudaStream_t s1;
    cudaEvent_t  e_fork, e_join;
    void*        cur_ptr;
    AsyncCtx() {
        cudaStreamCreateWithFlags(&s1, cudaStreamNonBlocking);
        cudaEventCreateWithFlags(&e_fork, cudaEventDisableTiming);
        cudaEventCreateWithFlags(&e_join, cudaEventDisableTiming);
        cudaGetSymbolAddress(&cur_ptr, g_cur);
        cudaFuncSetAttribute(k_gemm_tc, cudaFuncAttributeMaxDynamicSharedMemorySize,
                             GEMM_SMEM);
    }
};

extern "C" void kernel_launch(void* const* d_in, const int* in_sizes, int n_in,
                              void* d_out, int out_size) {
    static AsyncCtx ctx;   // built on first (non-captured) correctness call

    const float* x   = (const float*)d_in[0];
    const int*   src = (const int*)d_in[1];
    const int*   dst = (const int*)d_in[2];
    const float* W   = (const float*)d_in[3];
    const float* al  = (const float*)d_in[4];
    const float* ar  = (const float*)d_in[5];
    float* out = (float*)d_out;

    const int n = in_sizes[0] / D;     // 100000
    const int E = in_sizes[1];         // 1600000

    cudaEventRecord(ctx.e_fork, 0);
    cudaStreamWaitEvent(ctx.s1, ctx.e_fork, 0);

    // s1: bf16x3 tensor-core GEMM (+fused dots), M=128 tiles, 2 blocks/SM
    k_gemm_tc<<<(n + 127) / 128, 256, GEMM_SMEM, ctx.s1>>>(x, W, al, ar, n);
    cudaEventRecord(ctx.e_join, ctx.s1);

    // stream 0: direct binning
    cudaMemsetAsync(ctx.cur_ptr, 0, (size_t)n * sizeof(unsigned), 0);
    k_bin<<<(E + 255) / 256, 256>>>(src, dst, E);

    // join
    cudaStreamWaitEvent(0, ctx.e_join, 0);
    k_node<<<(n * 32 + 255) / 256, 256>>>(out, n);
}

// round 17
// speedup vs baseline: 1.3762x; 1.0750x over previous
#include <cuda_runtime.h>
#include <cuda_bf16.h>
#include <cuda_fp16.h>
#include <cstdint>

#define N_NODES 100000
#define N_EDGES 1600000
#define D 128
#define NEG_SLOPE 0.2f
#define BUCKET 96           // max degree supported; Poisson(16) => P(deg>96) ~ 1e-30
#define CAP 3               // BUCKET/32

// ---------------- scratch (device globals: no allocation allowed) ----------------
__device__ __half2  g_h16[(size_t)N_NODES * (D / 2)];  // 25.6 MB fp16 h (256B/row)
__device__ float    g_el[N_NODES];
__device__ float    g_er[N_NODES];
__device__ unsigned g_cur[N_NODES];                    // per-node fill cursor / degree
__device__ int      g_csrc[(size_t)N_NODES * BUCKET];  // 38.4 MB padded CSR

// ---------------- fp16 split helpers ----------------
__device__ __forceinline__ unsigned pack_h2(float a, float b) {
    __half2 h = __floats2half2_rn(a, b);
    return *(unsigned*)&h;
}
// A-side: (hi, lo) fp16x2 pair; combined ~22 mantissa bits
__device__ __forceinline__ uint2 split_pack_f16(float2 v) {
    __half2 hi = __floats2half2_rn(v.x, v.y);
    float2 hf = __half22float2(hi);
    unsigned lo = pack_h2(v.x - hf.x, v.y - hf.y);
    return make_uint2(*(unsigned*)&hi, lo);
}

__device__ __forceinline__ void mma_f16(float c[4], const unsigned a[4],
                                        unsigned b0, unsigned b1) {
    asm volatile(
        "mma.sync.aligned.m16n8k16.row.col.f32.f16.f16.f32 "
        "{%0,%1,%2,%3}, {%4,%5,%6,%7}, {%8,%9}, {%0,%1,%2,%3};"
        : "+f"(c[0]), "+f"(c[1]), "+f"(c[2]), "+f"(c[3])
        : "r"(a[0]), "r"(a[1]), "r"(a[2]), "r"(a[3]), "r"(b0), "r"(b1));
}

// ---------------- K1: h = x @ W^T via fp16x2 mma + fused el/er dots ----------------
// block = 256 threads (8 warps), 2 blocks/SM. Tile M=128 (16 rows/warp), N=128.
// K in 2 chunks of 64. A staged as fp16 (hi,lo) uint2 pairs; W staged as single
// fp16x2 plane (uint). 2 MMAs per k-step per n-tile: A_hi*B + A_lo*B.
// Strides 36 elements: A fragment LDS.64 banks (8g+2t), W fragment LDS.32 banks
// (4g+t) — both conflict-free per 16-lane phase.
#define CSTRIDE 36
#define CHUNK_KP 32   // k-pairs per chunk (64 K values)
#define GEMM_SMEM (128 * CSTRIDE * (8 + 4))   // A uint2 + W uint = 55296 B
__global__ __launch_bounds__(256, 2) void k_gemm_tc(const float* __restrict__ x,
                                                    const float* __restrict__ W,
                                                    const float* __restrict__ al,
                                                    const float* __restrict__ ar,
                                                    int n) {
    extern __shared__ char sraw[];
    uint2*    xs = (uint2*)sraw;                          // [128][CSTRIDE] uint2
    unsigned* ws = (unsigned*)(sraw + 128 * CSTRIDE * 8); // [128][CSTRIDE] uint
    const int tid = threadIdx.x;
    const int row0 = blockIdx.x * 128;

    const int wid = tid >> 5, lane = tid & 31;
    const int g = lane >> 2, t = lane & 3;
    const int m0 = wid * 16;
    const int rA = row0 + m0 + g;
    const int rB = rA + 8;
    const bool okA = rA < n, okB = rB < n;

    float c[16][4];
#pragma unroll
    for (int nt = 0; nt < 16; ++nt)
#pragma unroll
        for (int j = 0; j < 4; ++j) c[nt][j] = 0.0f;

#pragma unroll
    for (int ch = 0; ch < 2; ++ch) {
        const int col0 = ch * (CHUNK_KP * 2);   // float column base of this chunk

        // stage A chunk: 128 rows x 32 kp (fp16 hi/lo split)
#pragma unroll
        for (int i = 0; i < 16; ++i) {
            int idx = tid + i * 256;
            int r = idx >> 5, kp = idx & 31;
            int row = row0 + r;
            float2 v = (row < n) ? *(const float2*)(x + (size_t)row * D + col0 + kp * 2)
                                 : make_float2(0.f, 0.f);
            xs[r * CSTRIDE + kp] = split_pack_f16(v);
        }
        // stage W chunk: single fp16 plane
#pragma unroll
        for (int i = 0; i < 16; ++i) {
            int idx = tid + i * 256;
            int r = idx >> 5, kp = idx & 31;
            float2 v = *(const float2*)(W + (size_t)r * D + col0 + kp * 2);
            ws[r * CSTRIDE + kp] = pack_h2(v.x, v.y);
        }
        __syncthreads();

        const uint2* xrA = xs + (m0 + g) * CSTRIDE;
        const uint2* xrB = xs + (m0 + g + 8) * CSTRIDE;

#pragma unroll
        for (int kc = 0; kc < 4; ++kc) {
            const int kp0 = kc * 8 + t;
            uint2 pA0 = xrA[kp0], pB0 = xrB[kp0];
            uint2 pA4 = xrA[kp0 + 4], pB4 = xrB[kp0 + 4];
            unsigned ahi[4] = {pA0.x, pB0.x, pA4.x, pB4.x};
            unsigned alo[4] = {pA0.y, pB0.y, pA4.y, pB4.y};

            const unsigned* wrow = ws + g * CSTRIDE + kp0;
            // 2-nt interleave: same-accumulator MMAs are 2 apart
#pragma unroll
            for (int nt = 0; nt < 16; nt += 2) {
                unsigned b0a = wrow[0];
                unsigned b1a = wrow[4];
                unsigned b0b = wrow[8 * CSTRIDE];
                unsigned b1b = wrow[8 * CSTRIDE + 4];
                wrow += 16 * CSTRIDE;
                mma_f16(c[nt],     ahi, b0a, b1a);   // hi  nt
                mma_f16(c[nt + 1], ahi, b0b, b1b);   // hi  nt+1
                mma_f16(c[nt],     alo, b0a, b1a);   // lo  nt
                mma_f16(c[nt + 1], alo, b0b, b1b);   // lo  nt+1
            }
        }
        __syncthreads();
    }

    // epilogue: store h as fp16 + fused dots (C frag: rows rA/rB, cols nt*8+2t,+1)
    float plA = 0.f, prA = 0.f, plB = 0.f, prB = 0.f;
#pragma unroll
    for (int nt = 0; nt < 16; ++nt) {
        int col = nt * 8 + 2 * t;
        float2 av = *(const float2*)(al + col);
        float2 rv = *(const float2*)(ar + col);
        plA += c[nt][0] * av.x + c[nt][1] * av.y;
        prA += c[nt][0] * rv.x + c[nt][1] * rv.y;
        plB += c[nt][2] * av.x + c[nt][3] * av.y;
        prB += c[nt][2] * rv.x + c[nt][3] * rv.y;
        if (okA) g_h16[(size_t)rA * (D / 2) + (col >> 1)] =
                     __floats2half2_rn(c[nt][0], c[nt][1]);
        if (okB) g_h16[(size_t)rB * (D / 2) + (col >> 1)] =
                     __floats2half2_rn(c[nt][2], c[nt][3]);
    }
#pragma unroll
    for (int o = 1; o < 4; o <<= 1) {
        plA += __shfl_xor_sync(0xffffffffu, plA, o);
        prA += __shfl_xor_sync(0xffffffffu, prA, o);
        plB += __shfl_xor_sync(0xffffffffu, plB, o);
        prB += __shfl_xor_sync(0xffffffffu, prB, o);
    }
    if (t == 0) {
        if (okA) { g_el[rA] = plA; g_er[rA] = prA; }
        if (okB) { g_el[rB] = plB; g_er[rB] = prB; }
    }
}

// ---------------- K2: direct binning into padded buckets ----------------
__global__ void k_bin(const int* __restrict__ src, const int* __restrict__ dst, int E) {
    int i = blockIdx.x * blockDim.x + threadIdx.x;
    if (i < E) {
        int d = dst[i];
        unsigned slot = atomicAdd(&g_cur[d], 1u);
        if (slot < BUCKET) g_csrc[(size_t)d * BUCKET + slot] = src[i];
    }
}

// ---------------- K3: per-node softmax + weighted gather (1 warp / node) ----------------
// Gather phase: warp split into two 16-lane halves; each half owns alternate
// edges; each lane owns an 8-feature slice (uint4 = 8 fp16, LDG.128).
__global__ __launch_bounds__(256) void k_node(float* __restrict__ out, int n) {
    int node = (blockIdx.x * blockDim.x + threadIdx.x) >> 5;
    int lane = threadIdx.x & 31;
    if (node >= n) return;

    int deg = (int)g_cur[node];
    if (deg > BUCKET) deg = BUCKET;
    const int* bp = g_csrc + (size_t)node * BUCKET;
    float er_d = g_er[node];
    int nit = (deg + 31) >> 5;

    float exv[CAP];
    int   sv[CAP];
    float mx = __int_as_float(0xff800000);  // -inf

#pragma unroll
    for (int it = 0; it < CAP; ++it) {
        if (it >= nit) break;
        int k = it * 32 + lane;
        float e = __int_as_float(0xff800000);
        int s = 0;
        if (k < deg) {
            s = bp[k];
            e = g_el[s] + er_d;
            e = (e >= 0.0f) ? e : NEG_SLOPE * e;
        }
        sv[it] = s;
        exv[it] = e;
        mx = fmaxf(mx, e);
    }
#pragma unroll
    for (int o = 16; o > 0; o >>= 1)
        mx = fmaxf(mx, __shfl_xor_sync(0xffffffffu, mx, o));

    float den = 0.0f;
#pragma unroll
    for (int it = 0; it < CAP; ++it) {
        if (it >= nit) break;
        float ex = __expf(exv[it] - mx);
        exv[it] = ex;
        den += ex;
    }
#pragma unroll
    for (int o = 16; o > 0; o >>= 1)
        den += __shfl_xor_sync(0xffffffffu, den, o);
    float inv = 1.0f / fmaxf(den, 1e-38f);

    // ---- gather: 2 edges per step, 8-edge batches ----
    const int half = lane >> 4;         // 0/1: which edge of each pair
    const int fl   = lane & 15;         // feature slice: cols fl*8 .. fl*8+7
    const char* hbase = (const char*)g_h16;
    float acc[8];
#pragma unroll
    for (int j = 0; j < 8; ++j) acc[j] = 0.0f;

#pragma unroll
    for (int it = 0; it < CAP; ++it) {
        if (it >= nit) break;
        int cnt = deg - it * 32;
        if (cnt > 32) cnt = 32;
        float exn = exv[it];
        int   sn  = sv[it];
        for (int b = 0; b < cnt; b += 8) {
            float a[4]; int s[4];
#pragma unroll
            for (int j = 0; j < 4; ++j) {
                int e = b + 2 * j + half;           // <= 31
                float aa = __shfl_sync(0xffffffffu, exn, e) * inv;
                int   ss = __shfl_sync(0xffffffffu, sn, e);
                bool ok = e < cnt;
                a[j] = ok ? aa : 0.0f;
                s[j] = ok ? ss : 0;                 // row 0 valid; a=0 kills it
            }
            uint4 u[4];
#pragma unroll
            for (int j = 0; j < 4; ++j)
                u[j] = *(const uint4*)(hbase + (size_t)s[j] * 256 + fl * 16);
#pragma unroll
            for (int j = 0; j < 4; ++j) {
                float2 f0 = __half22float2(*(__half2*)&u[j].x);
                float2 f1 = __half22float2(*(__half2*)&u[j].y);
                float2 f2 = __half22float2(*(__half2*)&u[j].z);
                float2 f3 = __half22float2(*(__half2*)&u[j].w);
                acc[0] += a[j] * f0.x; acc[1] += a[j] * f0.y;
                acc[2] += a[j] * f1.x; acc[3] += a[j] * f1.y;
                acc[4] += a[j] * f2.x; acc[5] += a[j] * f2.y;
                acc[6] += a[j] * f3.x; acc[7] += a[j] * f3.y;
            }
        }
    }

    // merge the two halves (lane f and lane f+16 hold partial sums of same slice)
#pragma unroll
    for (int j = 0; j < 8; ++j)
        acc[j] += __shfl_xor_sync(0xffffffffu, acc[j], 16);

    if (half == 0) {
        float* op = out + (size_t)node * D + fl * 8;
        *(float4*)op       = make_float4(acc[0], acc[1], acc[2], acc[3]);
        *(float4*)(op + 4) = make_float4(acc[4], acc[5], acc[6], acc[7]);
    }
}

// ---------------- launch (two-stream fork/join, capture-safe) ----------------
struct AsyncCtx {
    cudaStream_t s1;
    cudaEvent_t  e_fork, e_join;
    void*        cur_ptr;
    AsyncCtx() {
        cudaStreamCreateWithFlags(&s1, cudaStreamNonBlocking);
        cudaEventCreateWithFlags(&e_fork, cudaEventDisableTiming);
        cudaEventCreateWithFlags(&e_join, cudaEventDisableTiming);
        cudaGetSymbolAddress(&cur_ptr, g_cur);
        cudaFuncSetAttribute(k_gemm_tc, cudaFuncAttributeMaxDynamicSharedMemorySize,
                             GEMM_SMEM);
    }
};

extern "C" void kernel_launch(void* const* d_in, const int* in_sizes, int n_in,
                              void* d_out, int out_size) {
    static AsyncCtx ctx;   // built on first (non-captured) correctness call

    const float* x   = (const float*)d_in[0];
    const int*   src = (const int*)d_in[1];
    const int*   dst = (const int*)d_in[2];
    const float* W   = (const float*)d_in[3];
    const float* al  = (const float*)d_in[4];
    const float* ar  = (const float*)d_in[5];
    float* out = (float*)d_out;

    const int n = in_sizes[0] / D;     // 100000
    const int E = in_sizes[1];         // 1600000

    cudaEventRecord(ctx.e_fork, 0);
    cudaStreamWaitEvent(ctx.s1, ctx.e_fork, 0);

    // s1: fp16x2-split tensor-core GEMM (+fused dots), M=128 tiles, 2 blocks/SM
    k_gemm_tc<<<(n + 127) / 128, 256, GEMM_SMEM, ctx.s1>>>(x, W, al, ar, n);
    cudaEventRecord(ctx.e_join, ctx.s1);

    // stream 0: direct binning
    cudaMemsetAsync(ctx.cur_ptr, 0, (size_t)n * sizeof(unsigned), 0);
    k_bin<<<(E + 255) / 256, 256>>>(src, dst, E);

    // join
    cudaStreamWaitEvent(0, ctx.e_join, 0);
    k_node<<<(n * 32 + 255) / 256, 256>>>(out, n);
}